// round 1
// baseline (speedup 1.0000x reference)
#include <cuda_runtime.h>
#include <cuda_bf16.h>
#include <math.h>

// Problem constants
#define PB 4
#define PC 32
#define PW 256
#define PH 256
#define PK 9
#define CENTER 4
#define EPS 1e-5f

#define NCO 10   // conv1 output channels actually needed (0..9)
#define NCOP 12  // padded to 12 for float4 weight loads

// ---------------- scratch (no allocations allowed) ----------------
__device__ float g_off[PB * NCO * PW * PH];   // conv1 raw output, ch 0..9
__device__ float g_py [PB * PK  * PW * PH];   // sample y coordinate (already clipped+scaled)
__device__ double g_s1a[PB * 5], g_s2a[PB * 5];   // GN1 sums (groups 0..4)
__device__ double g_s1b[PB * 8], g_s2b[PB * 8];   // GN2 sums (8 groups)
__device__ float g_A1[PB * NCO], g_B1[PB * NCO];
__device__ float g_A2[PB * PC],  g_B2[PB * PC];

// ---------------- helpers ----------------
__device__ __forceinline__ void block_reduce2_atomic(float v1, float v2,
                                                     double* d1, double* d2) {
    __shared__ float r1[8], r2[8];
    __syncthreads();  // protect r1/r2 reuse across calls
    #pragma unroll
    for (int o = 16; o; o >>= 1) {
        v1 += __shfl_down_sync(0xffffffffu, v1, o);
        v2 += __shfl_down_sync(0xffffffffu, v2, o);
    }
    int warp = threadIdx.x >> 5, lane = threadIdx.x & 31;
    if (lane == 0) { r1[warp] = v1; r2[warp] = v2; }
    __syncthreads();
    if (warp == 0) {
        v1 = (lane < 8) ? r1[lane] : 0.f;
        v2 = (lane < 8) ? r2[lane] : 0.f;
        #pragma unroll
        for (int o = 4; o; o >>= 1) {
            v1 += __shfl_down_sync(0xffffffffu, v1, o);
            v2 += __shfl_down_sync(0xffffffffu, v2, o);
        }
        if (lane == 0) { atomicAdd(d1, (double)v1); atomicAdd(d2, (double)v2); }
    }
}

// ---------------- K0: zero accumulators ----------------
__global__ void k_init() {
    int i = threadIdx.x;
    if (i < PB * 5) { g_s1a[i] = 0.0; g_s2a[i] = 0.0; }
    if (i < PB * 8) { g_s1b[i] = 0.0; g_s2b[i] = 0.0; }
}

// ---------------- K1: 3x3 SAME conv, channels 0..9, + GN1 partial sums ----
__global__ __launch_bounds__(256) void k_conv1(const float* __restrict__ x,
                                               const float* __restrict__ w_off,
                                               const float* __restrict__ b_off) {
    __shared__ __align__(16) float ws[PC][9][NCOP];  // [cin][tap][cout] 13824B
    __shared__ float xt[18][18];

    int tid = threadIdx.x;
    int b = blockIdx.z;
    int by = blockIdx.y * 16, bx = blockIdx.x * 16;

    // load weights transposed (pad cout 10->12 with zeros)
    for (int i = tid; i < PC * 9 * NCOP; i += 256) {
        int o = i % NCOP; int rest = i / NCOP;
        int tap = rest % 9; int cin = rest / 9;
        ws[cin][tap][o] = (o < NCO) ? w_off[(o * PC + cin) * 9 + tap] : 0.f;
    }

    int ty = tid >> 4, tx = tid & 15;
    int gi = by + ty, gj = bx + tx;   // gi: W index, gj: H index (contiguous)

    float a[NCOP];
    #pragma unroll
    for (int o = 0; o < NCOP; o++) a[o] = 0.f;

    const float* xb = x + (size_t)b * PC * PW * PH;

    for (int cin = 0; cin < PC; cin++) {
        __syncthreads();
        for (int i = tid; i < 324; i += 256) {
            int r = i / 18, c = i % 18;
            int yy = by + r - 1, xx = bx + c - 1;
            float v = 0.f;
            if (yy >= 0 && yy < PW && xx >= 0 && xx < PH)
                v = xb[cin * (PW * PH) + yy * PH + xx];
            xt[r][c] = v;
        }
        __syncthreads();
        #pragma unroll
        for (int di = 0; di < 3; di++) {
            #pragma unroll
            for (int dj = 0; dj < 3; dj++) {
                float xv = xt[ty + di][tx + dj];
                int tap = di * 3 + dj;
                const float4* wp = reinterpret_cast<const float4*>(&ws[cin][tap][0]);
                float4 wa = wp[0], wb = wp[1], wc = wp[2];
                a[0] += xv * wa.x; a[1] += xv * wa.y; a[2]  += xv * wa.z; a[3]  += xv * wa.w;
                a[4] += xv * wb.x; a[5] += xv * wb.y; a[6]  += xv * wb.z; a[7]  += xv * wb.w;
                a[8] += xv * wc.x; a[9] += xv * wc.y; a[10] += xv * wc.z; a[11] += xv * wc.w;
            }
        }
    }

    float p1[5], p2[5];
    #pragma unroll
    for (int g = 0; g < 5; g++) { p1[g] = 0.f; p2[g] = 0.f; }
    #pragma unroll
    for (int c = 0; c < NCO; c++) {
        float v = a[c] + b_off[c];
        g_off[(size_t)((b * NCO + c) << 16) + (gi << 8) + gj] = v;
        p1[c >> 1] += v;
        p2[c >> 1] += v * v;
    }
    for (int g = 0; g < 5; g++)
        block_reduce2_atomic(p1[g], p2[g], &g_s1a[b * 5 + g], &g_s2a[b * 5 + g]);
}

// ---------------- K1b: finalize GN1 -> per-channel affine ----------------
__global__ void k_fin1(const float* __restrict__ gos, const float* __restrict__ gob) {
    int i = threadIdx.x;
    if (i < PB * NCO) {
        int b = i / NCO, c = i % NCO, g = c >> 1;
        double N = 2.0 * PW * PH;
        double mu = g_s1a[b * 5 + g] / N;
        double var = g_s2a[b * 5 + g] / N - mu * mu;
        float rstd = rsqrtf((float)var + EPS);
        float A = gos[c] * rstd;
        g_A1[i] = A;
        g_B1[i] = gob[c] - (float)mu * A;
    }
}

// ---------------- K2: tanh(GN) + channel cumsum -> py field ----------------
__global__ __launch_bounds__(256) void k_py() {
    int pix = blockIdx.x * 256 + threadIdx.x;   // 0 .. 4*65536-1
    int b = pix >> 16;
    int w = (pix >> 8) & 255;
    int h = pix & 255;
    int base = (w << 8) + h;

    float t[PK];
    #pragma unroll
    for (int c = 0; c < PK; c++) {
        float v = g_off[(size_t)((b * NCO + c) << 16) + base];
        t[c] = tanhf(v * g_A1[b * NCO + c] + g_B1[b * NCO + c]);
    }
    float cum[PK];
    cum[3] = t[3];
    cum[2] = t[2] + cum[3];
    cum[1] = t[1] + cum[2];
    cum[0] = t[0] + cum[1];
    cum[4] = 0.f;
    cum[5] = t[5];
    cum[6] = cum[5] + t[6];
    cum[7] = cum[6] + t[7];
    cum[8] = cum[7] + t[8];

    #pragma unroll
    for (int k = 0; k < PK; k++) {
        float yn = (float)w + cum[k];
        float py = fminf(fmaxf(yn, 0.f), 256.f) * (255.0f / 256.0f);
        g_py[(size_t)((b * PK + k) << 16) + base] = py;
    }
}

// ---------------- K3: deformable gather + strided conv (the big GEMM) ------
#define K3_SMEM (PC * 9 * PC * 4 + 8 * 9 * 128 * 4 + 9 * 128 * 4)  // 78336 B

__global__ __launch_bounds__(256) void k_deform(const float* __restrict__ x,
                                                const float* __restrict__ w_dsc,
                                                const float* __restrict__ b_dsc,
                                                float* __restrict__ out) {
    extern __shared__ __align__(16) float smem[];
    float (*ws)[9][PC]  = (float (*)[9][PC])smem;                    // [32][9][32]
    float (*ds)[9][128] = (float (*)[9][128])(smem + PC * 9 * PC);   // [8][9][128]
    float (*pys)[128]   = (float (*)[128])(smem + PC * 9 * PC + 8 * 9 * 128);

    int tid = threadIdx.x;
    int w = blockIdx.x;
    int h0 = blockIdx.y * 128;
    int b = blockIdx.z;

    // weights: w_dsc[o][cin][k][0] -> ws[cin][k][o]
    for (int i = tid; i < PC * 9 * PC; i += 256) {
        int o = i & 31; int rest = i >> 5;
        int k = rest % 9; int cin = rest / 9;
        ws[cin][k][o] = w_dsc[(o * PC + cin) * 9 + k];
    }
    // py tile for this (b, w, h-range)
    for (int i = tid; i < 9 * 128; i += 256) {
        int k = i >> 7, hl = i & 127;
        pys[k][hl] = g_py[(size_t)((b * PK + k) << 16) + (w << 8) + h0 + hl];
    }

    int co = tid >> 5;   // 0..7  -> couts 4co..4co+3
    int ht = tid & 31;   // 0..31 -> h 4ht..4ht+3
    float acc[4][4];
    #pragma unroll
    for (int i = 0; i < 4; i++)
        #pragma unroll
        for (int j = 0; j < 4; j++) acc[i][j] = 0.f;

    const float* xb = x + ((size_t)(b * PC) << 16);

    for (int chunk = 0; chunk < 4; chunk++) {
        __syncthreads();
        int cin0 = chunk * 8;
        // gather phase: fill ds[8][9][128] with bilinear samples
        #pragma unroll 4
        for (int s = 0; s < 36; s++) {
            int idx = tid + (s << 8);
            int hl = idx & 127;
            int rest = idx >> 7;
            int k = rest % 9;
            int cl = rest / 9;

            float py = pys[k][hl];
            float y0f = floorf(py);
            float wy = py - y0f;
            int y0 = (int)y0f;
            int y1 = min(y0 + 1, 255);

            float pxn = (float)(h0 + hl + k - CENTER);
            float px = fminf(fmaxf(pxn, 0.f), 256.f) * (255.0f / 256.0f);
            float x0f = floorf(px);
            float wx = px - x0f;
            int x0 = (int)x0f;
            int x1 = min(x0 + 1, 255);

            const float* xp = xb + ((cin0 + cl) << 16);
            float v00 = xp[(y0 << 8) + x0];
            float v01 = xp[(y0 << 8) + x1];
            float v10 = xp[(y1 << 8) + x0];
            float v11 = xp[(y1 << 8) + x1];
            float vx0 = v00 + wx * (v01 - v00);
            float vx1 = v10 + wx * (v11 - v10);
            ds[cl][k][hl] = vx0 + wy * (vx1 - vx0);
        }
        __syncthreads();
        // compute phase: 8 cin x 9 k, 16 FMAs each
        for (int cl = 0; cl < 8; cl++) {
            #pragma unroll
            for (int k = 0; k < 9; k++) {
                float4 d4 = *(const float4*)&ds[cl][k][ht << 2];
                float4 w4 = *(const float4*)&ws[cin0 + cl][k][co << 2];
                acc[0][0] += w4.x * d4.x; acc[0][1] += w4.x * d4.y;
                acc[0][2] += w4.x * d4.z; acc[0][3] += w4.x * d4.w;
                acc[1][0] += w4.y * d4.x; acc[1][1] += w4.y * d4.y;
                acc[1][2] += w4.y * d4.z; acc[1][3] += w4.y * d4.w;
                acc[2][0] += w4.z * d4.x; acc[2][1] += w4.z * d4.y;
                acc[2][2] += w4.z * d4.z; acc[2][3] += w4.z * d4.w;
                acc[3][0] += w4.w * d4.x; acc[3][1] += w4.w * d4.y;
                acc[3][2] += w4.w * d4.z; acc[3][3] += w4.w * d4.w;
            }
        }
    }

    #pragma unroll
    for (int i = 0; i < 4; i++) {
        int o = (co << 2) + i;
        float bo = b_dsc[o];
        float4 r = make_float4(acc[i][0] + bo, acc[i][1] + bo,
                               acc[i][2] + bo, acc[i][3] + bo);
        *(float4*)&out[((size_t)(b * PC + o) << 16) + (w << 8) + h0 + (ht << 2)] = r;
    }
}

// ---------------- K4: GN2 partial sums from out2 ----------------
__global__ __launch_bounds__(256) void k_gn2(const float* __restrict__ out) {
    int idx = blockIdx.x;            // 512 = 4b * 8g * 16chunks
    int chunk = idx & 15;
    int g = (idx >> 4) & 7;
    int b = idx >> 7;
    size_t base = ((size_t)(b * PC + g * 4) << 16) + (size_t)chunk * 16384;
    float s1 = 0.f, s2 = 0.f;
    for (int i = threadIdx.x; i < 16384; i += 256) {
        float v = out[base + i];
        s1 += v; s2 += v * v;
    }
    block_reduce2_atomic(s1, s2, &g_s1b[b * 8 + g], &g_s2b[b * 8 + g]);
}

// ---------------- K4b: finalize GN2 ----------------
__global__ void k_fin2(const float* __restrict__ gs, const float* __restrict__ gb) {
    int i = threadIdx.x;
    if (i < PB * PC) {
        int b = i >> 5, c = i & 31, g = c >> 2;
        double N = 4.0 * PW * PH;
        double mu = g_s1b[b * 8 + g] / N;
        double var = g_s2b[b * 8 + g] / N - mu * mu;
        float rstd = rsqrtf((float)var + EPS);
        float A = gs[c] * rstd;
        g_A2[i] = A;
        g_B2[i] = gb[c] - (float)mu * A;
    }
}

// ---------------- K5: normalize + relu in place ----------------
__global__ __launch_bounds__(256) void k_relu(float* __restrict__ out) {
    int i4 = blockIdx.x * 256 + threadIdx.x;       // 2M float4
    int bc = i4 >> 14;                              // (b*32 + c), 16384 float4/channel
    float A = g_A2[bc], Bv = g_B2[bc];
    float4 v = ((float4*)out)[i4];
    v.x = fmaxf(v.x * A + Bv, 0.f);
    v.y = fmaxf(v.y * A + Bv, 0.f);
    v.z = fmaxf(v.z * A + Bv, 0.f);
    v.w = fmaxf(v.w * A + Bv, 0.f);
    ((float4*)out)[i4] = v;
}

// ---------------- launch ----------------
extern "C" void kernel_launch(void* const* d_in, const int* in_sizes, int n_in,
                              void* d_out, int out_size) {
    const float* x      = (const float*)d_in[0];
    const float* w_off  = (const float*)d_in[1];
    const float* b_off  = (const float*)d_in[2];
    const float* gos    = (const float*)d_in[3];
    const float* gob    = (const float*)d_in[4];
    const float* w_dsc  = (const float*)d_in[5];
    const float* b_dsc  = (const float*)d_in[6];
    const float* gs     = (const float*)d_in[7];
    const float* gb     = (const float*)d_in[8];
    float* out = (float*)d_out;

    cudaFuncSetAttribute(k_deform, cudaFuncAttributeMaxDynamicSharedMemorySize, K3_SMEM);

    k_init<<<1, 64>>>();
    k_conv1<<<dim3(16, 16, PB), 256>>>(x, w_off, b_off);
    k_fin1<<<1, 64>>>(gos, gob);
    k_py<<<1024, 256>>>();
    k_deform<<<dim3(256, 2, PB), 256, K3_SMEM>>>(x, w_dsc, b_dsc, out);
    k_gn2<<<512, 256>>>(out);
    k_fin2<<<1, 128>>>(gs, gb);
    k_relu<<<8192, 256>>>(out);
}

// round 2
// speedup vs baseline: 1.2376x; 1.2376x over previous
#include <cuda_runtime.h>
#include <cuda_bf16.h>
#include <math.h>

// Problem constants
#define PB 4
#define PC 32
#define PW 256
#define PH 256
#define PK 9
#define CENTER 4
#define EPS 1e-5f

#define NCO 10   // conv1 output channels actually needed (0..9)
#define NCOP 12  // padded to 12 for float4/f32x2 weight loads

typedef unsigned long long ull;

// ---------------- f32x2 helpers (FFMA2 — 2x fp32 rate on sm_103a) ----------
__device__ __forceinline__ ull pack2(float v) {
    ull r; asm("mov.b64 %0,{%1,%1};" : "=l"(r) : "f"(v)); return r;
}
__device__ __forceinline__ void fma2(ull& acc, ull a, ull b) {
    asm("fma.rn.f32x2 %0,%1,%2,%0;" : "+l"(acc) : "l"(a), "l"(b));
}
__device__ __forceinline__ float2 unpack2(ull v) {
    float2 f; asm("mov.b64 {%0,%1},%2;" : "=f"(f.x), "=f"(f.y) : "l"(v)); return f;
}

// ---------------- scratch (no allocations allowed) ----------------
__device__ float g_off[PB * NCO * PW * PH];   // conv1 raw output, ch 0..9
__device__ float g_py [PB * PK  * PW * PH];   // sample y coordinate (clipped+scaled)
__device__ double g_s1a[PB * 5], g_s2a[PB * 5];   // GN1 sums (groups 0..4)
__device__ double g_s1b[PB * 8], g_s2b[PB * 8];   // GN2 sums (8 groups)
__device__ float g_A1[PB * NCO], g_B1[PB * NCO];
__device__ float g_A2[PB * PC],  g_B2[PB * PC];

// ---------------- helpers ----------------
__device__ __forceinline__ void block_reduce2_atomic(float v1, float v2,
                                                     double* d1, double* d2) {
    __shared__ float r1[8], r2[8];
    __syncthreads();
    #pragma unroll
    for (int o = 16; o; o >>= 1) {
        v1 += __shfl_down_sync(0xffffffffu, v1, o);
        v2 += __shfl_down_sync(0xffffffffu, v2, o);
    }
    int warp = threadIdx.x >> 5, lane = threadIdx.x & 31;
    if (lane == 0) { r1[warp] = v1; r2[warp] = v2; }
    __syncthreads();
    if (warp == 0) {
        v1 = (lane < 8) ? r1[lane] : 0.f;
        v2 = (lane < 8) ? r2[lane] : 0.f;
        #pragma unroll
        for (int o = 4; o; o >>= 1) {
            v1 += __shfl_down_sync(0xffffffffu, v1, o);
            v2 += __shfl_down_sync(0xffffffffu, v2, o);
        }
        if (lane == 0) { atomicAdd(d1, (double)v1); atomicAdd(d2, (double)v2); }
    }
}

// ---------------- K0: zero accumulators ----------------
__global__ void k_init() {
    int i = threadIdx.x;
    if (i < PB * 5) { g_s1a[i] = 0.0; g_s2a[i] = 0.0; }
    if (i < PB * 8) { g_s1b[i] = 0.0; g_s2b[i] = 0.0; }
}

// ---------------- K1: 3x3 SAME conv (ch 0..9) + GN1 partial sums ----------
// tile: 32 (W-rows) x 16 (H-cols), 256 threads, 2 px/thread along H.
__global__ __launch_bounds__(256) void k_conv1(const float* __restrict__ x,
                                               const float* __restrict__ w_off,
                                               const float* __restrict__ b_off) {
    __shared__ __align__(16) float ws[PC][9][NCOP];  // [cin][tap][cout] 13824B
    __shared__ float xs[34][21];                     // halo tile, padded

    int tid = threadIdx.x;
    int b = blockIdx.z;
    int bw = blockIdx.y * 32;   // W offset
    int bh = blockIdx.x * 16;   // H offset

    // weights transposed (pad cout 10->12 with zeros)
    for (int i = tid; i < PC * 9 * NCOP; i += 256) {
        int o = i % NCOP; int rest = i / NCOP;
        int tap = rest % 9; int cin = rest / 9;
        ws[cin][tap][o] = (o < NCO) ? w_off[(o * PC + cin) * 9 + tap] : 0.f;
    }

    int ty = tid >> 3;            // 0..31 (W)
    int txh = (tid & 7) * 2;      // 0..14 (H, 2 px)
    int gi = bw + ty;

    ull acc[2][6];
    #pragma unroll
    for (int p = 0; p < 2; p++)
        #pragma unroll
        for (int q = 0; q < 6; q++) acc[p][q] = 0ull;

    const float* xb = x + (size_t)b * PC * PW * PH;

    for (int cin = 0; cin < PC; cin++) {
        __syncthreads();
        for (int i = tid; i < 34 * 18; i += 256) {
            int r = i / 18, c = i % 18;
            int yy = bw + r - 1, xx = bh + c - 1;
            float v = 0.f;
            if (yy >= 0 && yy < PW && xx >= 0 && xx < PH)
                v = xb[cin * (PW * PH) + yy * PH + xx];
            xs[r][c] = v;
        }
        __syncthreads();
        #pragma unroll
        for (int di = 0; di < 3; di++) {
            #pragma unroll
            for (int dj = 0; dj < 3; dj++) {
                const ulonglong2* wp =
                    reinterpret_cast<const ulonglong2*>(&ws[cin][di * 3 + dj][0]);
                ulonglong2 wa = wp[0], wb = wp[1], wc = wp[2];
                #pragma unroll
                for (int p = 0; p < 2; p++) {
                    ull xx2 = pack2(xs[ty + di][txh + p + dj]);
                    fma2(acc[p][0], wa.x, xx2);
                    fma2(acc[p][1], wa.y, xx2);
                    fma2(acc[p][2], wb.x, xx2);
                    fma2(acc[p][3], wb.y, xx2);
                    fma2(acc[p][4], wc.x, xx2);
                    fma2(acc[p][5], wc.y, xx2);
                }
            }
        }
    }

    float p1[5], p2[5];
    #pragma unroll
    for (int g = 0; g < 5; g++) { p1[g] = 0.f; p2[g] = 0.f; }
    #pragma unroll
    for (int p = 0; p < 2; p++) {
        int gj = bh + txh + p;
        #pragma unroll
        for (int q = 0; q < 5; q++) {      // pair q = GN group q (ch 2q, 2q+1)
            float2 f = unpack2(acc[p][q]);
            float v0 = f.x + b_off[2 * q];
            float v1 = f.y + b_off[2 * q + 1];
            g_off[(size_t)((b * NCO + 2 * q)     << 16) + (gi << 8) + gj] = v0;
            g_off[(size_t)((b * NCO + 2 * q + 1) << 16) + (gi << 8) + gj] = v1;
            p1[q] += v0 + v1;
            p2[q] += v0 * v0 + v1 * v1;
        }
    }
    for (int g = 0; g < 5; g++)
        block_reduce2_atomic(p1[g], p2[g], &g_s1a[b * 5 + g], &g_s2a[b * 5 + g]);
}

// ---------------- K1b: finalize GN1 -> per-channel affine ----------------
__global__ void k_fin1(const float* __restrict__ gos, const float* __restrict__ gob) {
    int i = threadIdx.x;
    if (i < PB * NCO) {
        int b = i / NCO, c = i % NCO, g = c >> 1;
        double N = 2.0 * PW * PH;
        double mu = g_s1a[b * 5 + g] / N;
        double var = g_s2a[b * 5 + g] / N - mu * mu;
        float rstd = rsqrtf((float)var + EPS);
        float A = gos[c] * rstd;
        g_A1[i] = A;
        g_B1[i] = gob[c] - (float)mu * A;
    }
}

// ---------------- K2: tanh(GN) + channel cumsum -> py field ----------------
__global__ __launch_bounds__(256) void k_py() {
    int pix = blockIdx.x * 256 + threadIdx.x;
    int b = pix >> 16;
    int w = (pix >> 8) & 255;
    int base = pix & 65535;

    float t[PK];
    #pragma unroll
    for (int c = 0; c < PK; c++) {
        float v = g_off[(size_t)((b * NCO + c) << 16) + base];
        t[c] = tanhf(v * g_A1[b * NCO + c] + g_B1[b * NCO + c]);
    }
    float cum[PK];
    cum[3] = t[3];
    cum[2] = t[2] + cum[3];
    cum[1] = t[1] + cum[2];
    cum[0] = t[0] + cum[1];
    cum[4] = 0.f;
    cum[5] = t[5];
    cum[6] = cum[5] + t[6];
    cum[7] = cum[6] + t[7];
    cum[8] = cum[7] + t[8];

    #pragma unroll
    for (int k = 0; k < PK; k++) {
        float yn = (float)w + cum[k];
        float py = fminf(fmaxf(yn, 0.f), 256.f) * (255.0f / 256.0f);
        g_py[(size_t)((b * PK + k) << 16) + base] = py;
    }
}

// ---------------- K3: deformable gather + strided conv (the big GEMM) ------
// Block = (w, b), full 256 h. cin chunks of 4. Thread tile 8 cout x 4 h.
// smem: ws[32][9][32] | ds_dup[4][9][256][2] | off4[9][256] int4 | wxy[9][256] f2
#define WS_FLOATS   (PC * 9 * PC)               // 9216
#define DS_FLOATS   (4 * 9 * 256 * 2)           // 18432
#define OFF4_INTS   (9 * 256 * 4)               // 9216
#define WXY_FLOATS  (9 * 256 * 2)               // 4608
#define K3_SMEM     ((WS_FLOATS + DS_FLOATS + OFF4_INTS + WXY_FLOATS) * 4) // 165888

__global__ __launch_bounds__(256) void k_deform(const float* __restrict__ x,
                                                const float* __restrict__ w_dsc,
                                                const float* __restrict__ b_dsc,
                                                float* __restrict__ out) {
    extern __shared__ __align__(16) float smem[];
    float* ws   = smem;                                  // [cin][k][co]
    ull*   dsd  = (ull*)(smem + WS_FLOATS);              // [cl][k][h] dup pairs
    int4*  off4 = (int4*)(smem + WS_FLOATS + DS_FLOATS); // [k][h]
    float2* wxy = (float2*)(smem + WS_FLOATS + DS_FLOATS + OFF4_INTS);

    int tid = threadIdx.x;
    int w = blockIdx.x;
    int b = blockIdx.y;

    // weights: w_dsc[o][cin][k][0] -> ws[(cin*9+k)*32+o]
    for (int i = tid; i < WS_FLOATS; i += 256) {
        int o = i & 31; int rest = i >> 5;
        int k = rest % 9; int cin = rest / 9;
        ws[(cin * 9 + k) * 32 + o] = w_dsc[(o * PC + cin) * 9 + k];
    }
    // per-(k,h) bilinear params
    for (int i = tid; i < 9 * 256; i += 256) {
        int k = i >> 8, h = i & 255;
        float py = g_py[(size_t)((b * PK + k) << 16) + (w << 8) + h];
        float y0f = floorf(py);
        float wy = py - y0f;
        int y0 = (int)y0f;
        int y1 = min(y0 + 1, 255);
        float pxn = (float)(h + k - CENTER);
        float px = fminf(fmaxf(pxn, 0.f), 256.f) * (255.0f / 256.0f);
        float x0f = floorf(px);
        float wx = px - x0f;
        int x0 = (int)x0f;
        int x1 = min(x0 + 1, 255);
        int o00 = (y0 << 8) + x0;
        off4[i] = make_int4(o00, (y0 << 8) + x1, (y1 << 8) + x0, (y1 << 8) + x1);
        wxy[i] = make_float2(wx, wy);
    }

    int co0 = (tid >> 6) * 8;       // 0,8,16,24
    int h0  = (tid & 63) * 4;       // 0..252
    ull acc[4][4];                  // [copair][h]
    #pragma unroll
    for (int p = 0; p < 4; p++)
        #pragma unroll
        for (int j = 0; j < 4; j++) acc[p][j] = 0ull;

    const float* xb = x + ((size_t)(b * PC) << 16);

    for (int chunk = 0; chunk < 8; chunk++) {
        int cin0 = chunk * 4;
        __syncthreads();
        // gather: 4 cin x 9 k x 256 h = 9216 samples, 36/thread
        #pragma unroll 4
        for (int s = 0; s < 36; s++) {
            int idx = tid + (s << 8);
            int h = idx & 255;
            int r = idx >> 8;
            int k = r % 9;
            int cl = r / 9;
            int4 o = off4[(k << 8) + h];
            float2 ww = wxy[(k << 8) + h];
            const float* xp = xb + ((cin0 + cl) << 16);
            float v00 = xp[o.x];
            float v01 = xp[o.y];
            float v10 = xp[o.z];
            float v11 = xp[o.w];
            float vx0 = v00 + ww.x * (v01 - v00);
            float vx1 = v10 + ww.x * (v11 - v10);
            float v = vx0 + ww.y * (vx1 - vx0);
            dsd[((cl * 9 + k) << 8) + h] = pack2(v);
        }
        __syncthreads();
        // compute: 4 cin x 9 k, 16 FFMA2 (=32 FMA) each
        #pragma unroll
        for (int cl = 0; cl < 4; cl++) {
            #pragma unroll
            for (int k = 0; k < 9; k++) {
                const ulonglong2* wp =
                    (const ulonglong2*)&ws[((cin0 + cl) * 9 + k) * 32 + co0];
                ulonglong2 wA = wp[0];   // copairs 0,1
                ulonglong2 wB = wp[1];   // copairs 2,3
                const ulonglong2* dp =
                    (const ulonglong2*)&dsd[((cl * 9 + k) << 8) + h0];
                ulonglong2 dA = dp[0];   // {d(h0),d(h0)},{d(h0+1),d(h0+1)}
                ulonglong2 dB = dp[1];
                fma2(acc[0][0], wA.x, dA.x); fma2(acc[1][0], wA.y, dA.x);
                fma2(acc[2][0], wB.x, dA.x); fma2(acc[3][0], wB.y, dA.x);
                fma2(acc[0][1], wA.x, dA.y); fma2(acc[1][1], wA.y, dA.y);
                fma2(acc[2][1], wB.x, dA.y); fma2(acc[3][1], wB.y, dA.y);
                fma2(acc[0][2], wA.x, dB.x); fma2(acc[1][2], wA.y, dB.x);
                fma2(acc[2][2], wB.x, dB.x); fma2(acc[3][2], wB.y, dB.x);
                fma2(acc[0][3], wA.x, dB.y); fma2(acc[1][3], wA.y, dB.y);
                fma2(acc[2][3], wB.x, dB.y); fma2(acc[3][3], wB.y, dB.y);
            }
        }
    }

    #pragma unroll
    for (int p = 0; p < 4; p++) {
        int oc0 = co0 + 2 * p;
        float b0 = b_dsc[oc0], b1 = b_dsc[oc0 + 1];
        float2 f0 = unpack2(acc[p][0]);
        float2 f1 = unpack2(acc[p][1]);
        float2 f2 = unpack2(acc[p][2]);
        float2 f3 = unpack2(acc[p][3]);
        float4 r0 = make_float4(f0.x + b0, f1.x + b0, f2.x + b0, f3.x + b0);
        float4 r1 = make_float4(f0.y + b1, f1.y + b1, f2.y + b1, f3.y + b1);
        *(float4*)&out[((size_t)(b * PC + oc0)     << 16) + (w << 8) + h0] = r0;
        *(float4*)&out[((size_t)(b * PC + oc0 + 1) << 16) + (w << 8) + h0] = r1;
    }
}

// ---------------- K4: GN2 partial sums ----------------
__global__ __launch_bounds__(256) void k_gn2(const float* __restrict__ out) {
    int idx = blockIdx.x;            // 512 = 4b * 8g * 16chunks
    int chunk = idx & 15;
    int g = (idx >> 4) & 7;
    int b = idx >> 7;
    size_t base = ((size_t)(b * PC + g * 4) << 16) + (size_t)chunk * 16384;
    float s1 = 0.f, s2 = 0.f;
    for (int i = threadIdx.x; i < 16384; i += 256) {
        float v = out[base + i];
        s1 += v; s2 += v * v;
    }
    block_reduce2_atomic(s1, s2, &g_s1b[b * 8 + g], &g_s2b[b * 8 + g]);
}

// ---------------- K4b: finalize GN2 ----------------
__global__ void k_fin2(const float* __restrict__ gs, const float* __restrict__ gb) {
    int i = threadIdx.x;
    if (i < PB * PC) {
        int b = i >> 5, c = i & 31, g = c >> 2;
        double N = 4.0 * PW * PH;
        double mu = g_s1b[b * 8 + g] / N;
        double var = g_s2b[b * 8 + g] / N - mu * mu;
        float rstd = rsqrtf((float)var + EPS);
        float A = gs[c] * rstd;
        g_A2[i] = A;
        g_B2[i] = gb[c] - (float)mu * A;
    }
}

// ---------------- K5: normalize + relu in place ----------------
__global__ __launch_bounds__(256) void k_relu(float* __restrict__ out) {
    int i4 = blockIdx.x * 256 + threadIdx.x;
    int bc = i4 >> 14;
    float A = g_A2[bc], Bv = g_B2[bc];
    float4 v = ((float4*)out)[i4];
    v.x = fmaxf(v.x * A + Bv, 0.f);
    v.y = fmaxf(v.y * A + Bv, 0.f);
    v.z = fmaxf(v.z * A + Bv, 0.f);
    v.w = fmaxf(v.w * A + Bv, 0.f);
    ((float4*)out)[i4] = v;
}

// ---------------- launch ----------------
extern "C" void kernel_launch(void* const* d_in, const int* in_sizes, int n_in,
                              void* d_out, int out_size) {
    const float* x      = (const float*)d_in[0];
    const float* w_off  = (const float*)d_in[1];
    const float* b_off  = (const float*)d_in[2];
    const float* gos    = (const float*)d_in[3];
    const float* gob    = (const float*)d_in[4];
    const float* w_dsc  = (const float*)d_in[5];
    const float* b_dsc  = (const float*)d_in[6];
    const float* gs     = (const float*)d_in[7];
    const float* gb     = (const float*)d_in[8];
    float* out = (float*)d_out;

    cudaFuncSetAttribute(k_deform, cudaFuncAttributeMaxDynamicSharedMemorySize, K3_SMEM);

    k_init<<<1, 64>>>();
    k_conv1<<<dim3(16, 8, PB), 256>>>(x, w_off, b_off);
    k_fin1<<<1, 64>>>(gos, gob);
    k_py<<<1024, 256>>>();
    k_deform<<<dim3(256, PB), 256, K3_SMEM>>>(x, w_dsc, b_dsc, out);
    k_gn2<<<512, 256>>>(out);
    k_fin2<<<1, 128>>>(gs, gb);
    k_relu<<<8192, 256>>>(out);
}

// round 4
// speedup vs baseline: 2.9838x; 2.4109x over previous
#include <cuda_runtime.h>
#include <cuda_bf16.h>
#include <math.h>

// Problem constants
#define PB 4
#define PC 32
#define PW 256
#define PH 256
#define PK 9
#define CENTER 4
#define EPS 1e-5f

#define NCO 10   // conv1 output channels actually needed (0..9)
#define NCOP 12  // padded to 12 for f32x2 weight loads
#define RROWS 11 // rows staged per (b,w) block: y in [w-5, w+5]

typedef unsigned long long ull;
typedef unsigned char uchar;

// ---------------- f32x2 helpers (FFMA2 — 2x fp32 rate on sm_103a) ----------
__device__ __forceinline__ ull pack2(float v) {
    ull r; asm("mov.b64 %0,{%1,%1};" : "=l"(r) : "f"(v)); return r;
}
__device__ __forceinline__ void fma2(ull& acc, ull a, ull b) {
    asm("fma.rn.f32x2 %0,%1,%2,%0;" : "+l"(acc) : "l"(a), "l"(b));
}
__device__ __forceinline__ float2 unpack2(ull v) {
    float2 f; asm("mov.b64 {%0,%1},%2;" : "=f"(f.x), "=f"(f.y) : "l"(v)); return f;
}
__device__ __forceinline__ void cp16(unsigned sdst, const void* gsrc) {
    asm volatile("cp.async.cg.shared.global [%0], [%1], 16;" :: "r"(sdst), "l"(gsrc));
}
__device__ __forceinline__ unsigned s2u(const void* p) {
    unsigned a;
    asm("{ .reg .u64 t; cvta.to.shared.u64 t, %1; cvt.u32.u64 %0, t; }" : "=r"(a) : "l"(p));
    return a;
}

// ---------------- scratch ----------------
__device__ float g_off[PB * NCO * PW * PH];
__device__ float g_py [PB * PK  * PW * PH];
__device__ ull   g_wsd[PC * PK * PC];            // dup'd deform weights [cin][k][cout]
__device__ double g_s1a[PB * 5], g_s2a[PB * 5];
__device__ double g_s1b[PB * 8], g_s2b[PB * 8];
__device__ float g_A1[PB * NCO], g_B1[PB * NCO];
__device__ float g_A2[PB * PC],  g_B2[PB * PC];

// ---------------- helpers ----------------
__device__ __forceinline__ void block_reduce2_atomic(float v1, float v2,
                                                     double* d1, double* d2) {
    __shared__ float r1[8], r2[8];
    __syncthreads();
    #pragma unroll
    for (int o = 16; o; o >>= 1) {
        v1 += __shfl_down_sync(0xffffffffu, v1, o);
        v2 += __shfl_down_sync(0xffffffffu, v2, o);
    }
    int warp = threadIdx.x >> 5, lane = threadIdx.x & 31;
    if (lane == 0) { r1[warp] = v1; r2[warp] = v2; }
    __syncthreads();
    if (warp == 0) {
        v1 = (lane < 8) ? r1[lane] : 0.f;
        v2 = (lane < 8) ? r2[lane] : 0.f;
        #pragma unroll
        for (int o = 4; o; o >>= 1) {
            v1 += __shfl_down_sync(0xffffffffu, v1, o);
            v2 += __shfl_down_sync(0xffffffffu, v2, o);
        }
        if (lane == 0) { atomicAdd(d1, (double)v1); atomicAdd(d2, (double)v2); }
    }
}

// warp-level: destination must be uniform WITHIN a warp (it is: co0 = f(tid>>6))
__device__ __forceinline__ void warp_reduce2_atomic(float v1, float v2,
                                                    double* d1, double* d2) {
    #pragma unroll
    for (int o = 16; o; o >>= 1) {
        v1 += __shfl_down_sync(0xffffffffu, v1, o);
        v2 += __shfl_down_sync(0xffffffffu, v2, o);
    }
    if ((threadIdx.x & 31) == 0) {
        atomicAdd(d1, (double)v1);
        atomicAdd(d2, (double)v2);
    }
}

// ---------------- K0: zero accumulators ----------------
__global__ void k_init() {
    int i = threadIdx.x;
    if (i < PB * 5) { g_s1a[i] = 0.0; g_s2a[i] = 0.0; }
    if (i < PB * 8) { g_s1b[i] = 0.0; g_s2b[i] = 0.0; }
}

// ---------------- K0b: transpose+duplicate deform weights (one-time) -------
__global__ void k_prew(const float* __restrict__ w_dsc) {
    int i = blockIdx.x * 256 + threadIdx.x;     // (cin*9+k)*32+o
    if (i < PC * PK * PC) {
        int o = i & 31; int r = i >> 5;
        int k = r % 9; int cin = r / 9;
        g_wsd[i] = pack2(w_dsc[(o * PC + cin) * 9 + k]);
    }
}

// ---------------- K1: 3x3 SAME conv (ch 0..9) + GN1 partial sums ----------
__global__ __launch_bounds__(256) void k_conv1(const float* __restrict__ x,
                                               const float* __restrict__ w_off,
                                               const float* __restrict__ b_off) {
    __shared__ __align__(16) float ws[PC][9][NCOP];
    __shared__ float xs[34][21];

    int tid = threadIdx.x;
    int b = blockIdx.z;
    int bw = blockIdx.y * 32;
    int bh = blockIdx.x * 16;

    for (int i = tid; i < PC * 9 * NCOP; i += 256) {
        int o = i % NCOP; int rest = i / NCOP;
        int tap = rest % 9; int cin = rest / 9;
        ws[cin][tap][o] = (o < NCO) ? w_off[(o * PC + cin) * 9 + tap] : 0.f;
    }

    int ty = tid >> 3;
    int txh = (tid & 7) * 2;
    int gi = bw + ty;

    ull acc[2][6];
    #pragma unroll
    for (int p = 0; p < 2; p++)
        #pragma unroll
        for (int q = 0; q < 6; q++) acc[p][q] = 0ull;

    const float* xb = x + (size_t)b * PC * PW * PH;

    for (int cin = 0; cin < PC; cin++) {
        __syncthreads();
        for (int i = tid; i < 34 * 18; i += 256) {
            int r = i / 18, c = i % 18;
            int yy = bw + r - 1, xx = bh + c - 1;
            float v = 0.f;
            if (yy >= 0 && yy < PW && xx >= 0 && xx < PH)
                v = xb[cin * (PW * PH) + yy * PH + xx];
            xs[r][c] = v;
        }
        __syncthreads();
        #pragma unroll
        for (int di = 0; di < 3; di++) {
            #pragma unroll
            for (int dj = 0; dj < 3; dj++) {
                const ulonglong2* wp =
                    reinterpret_cast<const ulonglong2*>(&ws[cin][di * 3 + dj][0]);
                ulonglong2 wa = wp[0], wb = wp[1], wc = wp[2];
                #pragma unroll
                for (int p = 0; p < 2; p++) {
                    ull xx2 = pack2(xs[ty + di][txh + p + dj]);
                    fma2(acc[p][0], wa.x, xx2);
                    fma2(acc[p][1], wa.y, xx2);
                    fma2(acc[p][2], wb.x, xx2);
                    fma2(acc[p][3], wb.y, xx2);
                    fma2(acc[p][4], wc.x, xx2);
                    fma2(acc[p][5], wc.y, xx2);
                }
            }
        }
    }

    float p1[5], p2[5];
    #pragma unroll
    for (int g = 0; g < 5; g++) { p1[g] = 0.f; p2[g] = 0.f; }
    #pragma unroll
    for (int p = 0; p < 2; p++) {
        int gj = bh + txh + p;
        #pragma unroll
        for (int q = 0; q < 5; q++) {
            float2 f = unpack2(acc[p][q]);
            float v0 = f.x + b_off[2 * q];
            float v1 = f.y + b_off[2 * q + 1];
            g_off[(size_t)((b * NCO + 2 * q)     << 16) + (gi << 8) + gj] = v0;
            g_off[(size_t)((b * NCO + 2 * q + 1) << 16) + (gi << 8) + gj] = v1;
            p1[q] += v0 + v1;
            p2[q] += v0 * v0 + v1 * v1;
        }
    }
    for (int g = 0; g < 5; g++)
        block_reduce2_atomic(p1[g], p2[g], &g_s1a[b * 5 + g], &g_s2a[b * 5 + g]);
}

// ---------------- K1b: finalize GN1 ----------------
__global__ void k_fin1(const float* __restrict__ gos, const float* __restrict__ gob) {
    int i = threadIdx.x;
    if (i < PB * NCO) {
        int b = i / NCO, c = i % NCO, g = c >> 1;
        double N = 2.0 * PW * PH;
        double mu = g_s1a[b * 5 + g] / N;
        double var = g_s2a[b * 5 + g] / N - mu * mu;
        float rstd = rsqrtf((float)var + EPS);
        float A = gos[c] * rstd;
        g_A1[i] = A;
        g_B1[i] = gob[c] - (float)mu * A;
    }
}

// ---------------- K2: tanh(GN) + channel cumsum -> py field ----------------
__global__ __launch_bounds__(256) void k_py() {
    int pix = blockIdx.x * 256 + threadIdx.x;
    int b = pix >> 16;
    int w = (pix >> 8) & 255;
    int base = pix & 65535;

    float t[PK];
    #pragma unroll
    for (int c = 0; c < PK; c++) {
        float v = g_off[(size_t)((b * NCO + c) << 16) + base];
        t[c] = tanhf(v * g_A1[b * NCO + c] + g_B1[b * NCO + c]);
    }
    float cum[PK];
    cum[3] = t[3];
    cum[2] = t[2] + cum[3];
    cum[1] = t[1] + cum[2];
    cum[0] = t[0] + cum[1];
    cum[4] = 0.f;
    cum[5] = t[5];
    cum[6] = cum[5] + t[6];
    cum[7] = cum[6] + t[7];
    cum[8] = cum[7] + t[8];

    #pragma unroll
    for (int k = 0; k < PK; k++) {
        float yn = (float)w + cum[k];
        float py = fminf(fmaxf(yn, 0.f), 256.f) * (255.0f / 256.0f);
        g_py[(size_t)((b * PK + k) << 16) + base] = py;
    }
}

// ---------------- K3: deformable gather + strided conv (big GEMM) ----------
// Block=(w,b). SMEM bytes:
//   ds   [4][9][256] f32        @ 0      (36864)
//   rows [4][11][256] f32       @ 36864  (45056)
//   wyv  [9][256] f32           @ 81920  (9216)
//   pr   [9][256] u8            @ 91136  (2304)
//   wsd  [2][4*9*32] ull (dup)  @ 93440  (18432)
#define DS_OFF   0
#define ROWS_OFF 36864
#define WY_OFF   81920
#define PR_OFF   91136
#define WSD_OFF  93440
#define K3_SMEM  111872

__global__ __launch_bounds__(256, 2) void k_deform(const float* __restrict__ x,
                                                   const float* __restrict__ b_dsc,
                                                   float* __restrict__ out) {
    extern __shared__ __align__(16) char smem[];
    float* ds   = (float*)(smem + DS_OFF);
    float* rows = (float*)(smem + ROWS_OFF);
    float* wyv  = (float*)(smem + WY_OFF);
    uchar* pr   = (uchar*)(smem + PR_OFF);
    ull*   wsd  = (ull*)  (smem + WSD_OFF);
    unsigned su = s2u(smem);

    int tid = threadIdx.x;
    int w = blockIdx.x;
    int b = blockIdx.y;
    const float* xb = x + ((size_t)(b * PC) << 16);

    // ---- per-(k,h) params from py ----
    for (int i = tid; i < PK * 256; i += 256) {
        int k = i >> 8;
        float py = g_py[(size_t)((b * PK + k) << 16) + (w << 8) + (i & 255)];
        float y0f = floorf(py);
        wyv[i] = py - y0f;
        pr[i] = (uchar)((int)y0f - (w - 5));    // in [0,10]
    }

    // ---- staging (cp.async) ----
    auto stage = [&](int c) {
        int cin0 = c * 4;
        #pragma unroll
        for (int j = 0; j < 11; j++) {
            int i4 = tid + j * 256;             // < 2816
            int rid = i4 >> 6;                  // cl*11+rr
            int c4 = i4 & 63;
            int cl = rid / 11;
            int rr = rid - cl * 11;
            int g = min(max(w - 5 + rr, 0), 255);
            cp16(su + ROWS_OFF + ((rid << 8) + (c4 << 2)) * 4,
                 xb + (((size_t)(cin0 + cl)) << 16) + (g << 8) + (c4 << 2));
        }
        #pragma unroll
        for (int j = 0; j < 3; j++) {
            int i = tid + j * 256;
            if (i < 576)
                cp16(su + WSD_OFF + ((c & 1) * 1152 + i * 2) * 8,
                     g_wsd + cin0 * 9 * 32 + i * 2);
        }
        asm volatile("cp.async.commit_group;");
    };

    int co0 = (tid >> 6) * 8;       // uniform per 64-thread group (so per warp)
    int h0  = (tid & 63) * 4;
    ull acc[8][2];
    #pragma unroll
    for (int i = 0; i < 8; i++) { acc[i][0] = 0ull; acc[i][1] = 0ull; }

    stage(0);

    for (int c = 0; c < 8; c++) {
        asm volatile("cp.async.wait_group 0;");
        __syncthreads();                         // rows/ws ready; ds free

        // ---- gather from staged rows (conflict-free LDS) ----
        #pragma unroll
        for (int k = 0; k < PK; k++) {
            float wy = wyv[(k << 8) + tid];
            int r0 = pr[(k << 8) + tid];
            int r1 = min(r0 + 1, 260 - w);
            int t = min(max(tid + k - CENTER, 0), 256);
            float px = (float)t * (255.0f / 256.0f);
            int x0 = (int)px;
            float wx = px - (float)x0;
            int x1 = min(x0 + 1, 255);
            #pragma unroll
            for (int cl = 0; cl < 4; cl++) {
                const float* rp0 = rows + ((cl * RROWS + r0) << 8);
                const float* rp1 = rows + ((cl * RROWS + r1) << 8);
                float v00 = rp0[x0], v01 = rp0[x1];
                float v10 = rp1[x0], v11 = rp1[x1];
                float vx0 = v00 + wx * (v01 - v00);
                float vx1 = v10 + wx * (v11 - v10);
                ds[((cl * 9 + k) << 8) + tid] = vx0 + wy * (vx1 - vx0);
            }
        }
        __syncthreads();                         // ds ready; rows consumed
        if (c < 7) stage(c + 1);

        // ---- GEMM: h-paired FFMA2, broadcast dup'd weights ----
        const ull* wb = wsd + (c & 1) * 1152;
        #pragma unroll
        for (int cl = 0; cl < 4; cl++) {
            #pragma unroll
            for (int k = 0; k < 9; k++) {
                const ull* wp = wb + ((cl * 9 + k) << 5) + co0;
                ulonglong2 wa = *(const ulonglong2*)(wp);
                ulonglong2 wbb = *(const ulonglong2*)(wp + 2);
                ulonglong2 wc = *(const ulonglong2*)(wp + 4);
                ulonglong2 wd = *(const ulonglong2*)(wp + 6);
                ulonglong2 dv = *(const ulonglong2*)(ds + ((cl * 9 + k) << 8) + h0);
                fma2(acc[0][0], wa.x, dv.x);  fma2(acc[0][1], wa.x, dv.y);
                fma2(acc[1][0], wa.y, dv.x);  fma2(acc[1][1], wa.y, dv.y);
                fma2(acc[2][0], wbb.x, dv.x); fma2(acc[2][1], wbb.x, dv.y);
                fma2(acc[3][0], wbb.y, dv.x); fma2(acc[3][1], wbb.y, dv.y);
                fma2(acc[4][0], wc.x, dv.x);  fma2(acc[4][1], wc.x, dv.y);
                fma2(acc[5][0], wc.y, dv.x);  fma2(acc[5][1], wc.y, dv.y);
                fma2(acc[6][0], wd.x, dv.x);  fma2(acc[6][1], wd.x, dv.y);
                fma2(acc[7][0], wd.y, dv.x);  fma2(acc[7][1], wd.y, dv.y);
            }
        }
    }

    // ---- epilogue: bias, store, fused GN2 partial sums (warp-level!) ----
    float sa1 = 0.f, sa2 = 0.f, sb1 = 0.f, sb2 = 0.f;
    #pragma unroll
    for (int i = 0; i < 8; i++) {
        int o = co0 + i;
        float bo = b_dsc[o];
        float2 f01 = unpack2(acc[i][0]);
        float2 f23 = unpack2(acc[i][1]);
        float v0 = f01.x + bo, v1 = f01.y + bo;
        float v2 = f23.x + bo, v3 = f23.y + bo;
        float4 r = make_float4(v0, v1, v2, v3);
        *(float4*)&out[((size_t)(b * PC + o) << 16) + (w << 8) + h0] = r;
        float s = v0 + v1 + v2 + v3;
        float q = v0 * v0 + v1 * v1 + v2 * v2 + v3 * v3;
        if (i < 4) { sa1 += s; sa2 += q; } else { sb1 += s; sb2 += q; }
    }
    int g0 = co0 >> 2;   // warp-uniform: groups g0 (couts co0..co0+3) and g0+1
    warp_reduce2_atomic(sa1, sa2, &g_s1b[b * 8 + g0],     &g_s2b[b * 8 + g0]);
    warp_reduce2_atomic(sb1, sb2, &g_s1b[b * 8 + g0 + 1], &g_s2b[b * 8 + g0 + 1]);
}

// ---------------- K4b: finalize GN2 ----------------
__global__ void k_fin2(const float* __restrict__ gs, const float* __restrict__ gb) {
    int i = threadIdx.x;
    if (i < PB * PC) {
        int b = i >> 5, c = i & 31, g = c >> 2;
        double N = 4.0 * PW * PH;
        double mu = g_s1b[b * 8 + g] / N;
        double var = g_s2b[b * 8 + g] / N - mu * mu;
        float rstd = rsqrtf((float)var + EPS);
        float A = gs[c] * rstd;
        g_A2[i] = A;
        g_B2[i] = gb[c] - (float)mu * A;
    }
}

// ---------------- K5: normalize + relu in place ----------------
__global__ __launch_bounds__(256) void k_relu(float* __restrict__ out) {
    int i4 = blockIdx.x * 256 + threadIdx.x;
    int bc = i4 >> 14;
    float A = g_A2[bc], Bv = g_B2[bc];
    float4 v = ((float4*)out)[i4];
    v.x = fmaxf(v.x * A + Bv, 0.f);
    v.y = fmaxf(v.y * A + Bv, 0.f);
    v.z = fmaxf(v.z * A + Bv, 0.f);
    v.w = fmaxf(v.w * A + Bv, 0.f);
    ((float4*)out)[i4] = v;
}

// ---------------- launch ----------------
extern "C" void kernel_launch(void* const* d_in, const int* in_sizes, int n_in,
                              void* d_out, int out_size) {
    const float* x      = (const float*)d_in[0];
    const float* w_off  = (const float*)d_in[1];
    const float* b_off  = (const float*)d_in[2];
    const float* gos    = (const float*)d_in[3];
    const float* gob    = (const float*)d_in[4];
    const float* w_dsc  = (const float*)d_in[5];
    const float* b_dsc  = (const float*)d_in[6];
    const float* gs     = (const float*)d_in[7];
    const float* gb     = (const float*)d_in[8];
    float* out = (float*)d_out;

    cudaFuncSetAttribute(k_deform, cudaFuncAttributeMaxDynamicSharedMemorySize, K3_SMEM);

    k_init<<<1, 64>>>();
    k_prew<<<36, 256>>>(w_dsc);
    k_conv1<<<dim3(16, 8, PB), 256>>>(x, w_off, b_off);
    k_fin1<<<1, 64>>>(gos, gob);
    k_py<<<1024, 256>>>();
    k_deform<<<dim3(256, PB), 256, K3_SMEM>>>(x, b_dsc, out);
    k_fin2<<<1, 128>>>(gs, gb);
    k_relu<<<8192, 256>>>(out);
}

// round 6
// speedup vs baseline: 3.1848x; 1.0674x over previous
#include <cuda_runtime.h>
#include <cuda_bf16.h>
#include <math.h>

// Problem constants
#define PB 4
#define PC 32
#define PW 256
#define PH 256
#define PK 9
#define CENTER 4
#define EPS 1e-5f

#define NCO 10   // conv1 output channels needed (0..9): 9 for py + ch9 for GN stats
#define RROWS 11 // rows staged per (b,w) deform block: y in [w-5, w+5]

typedef unsigned long long ull;
typedef unsigned char uchar;

// ---------------- f32x2 helpers (FFMA2 — 2x fp32 rate on sm_103a) ----------
__device__ __forceinline__ ull pack2(float v) {
    ull r; asm("mov.b64 %0,{%1,%1};" : "=l"(r) : "f"(v)); return r;
}
__device__ __forceinline__ void fma2(ull& acc, ull a, ull b) {
    asm("fma.rn.f32x2 %0,%1,%2,%0;" : "+l"(acc) : "l"(a), "l"(b));
}
__device__ __forceinline__ float2 unpack2(ull v) {
    float2 f; asm("mov.b64 {%0,%1},%2;" : "=f"(f.x), "=f"(f.y) : "l"(v)); return f;
}
__device__ __forceinline__ void cp16(unsigned sdst, const void* gsrc) {
    asm volatile("cp.async.cg.shared.global [%0], [%1], 16;" :: "r"(sdst), "l"(gsrc));
}
__device__ __forceinline__ unsigned s2u(const void* p) {
    unsigned a;
    asm("{ .reg .u64 t; cvta.to.shared.u64 t, %1; cvt.u32.u64 %0, t; }" : "=r"(a) : "l"(p));
    return a;
}

// ---------------- scratch ----------------
__device__ float g_off[PB * NCO * PW * PH];
__device__ ull   g_wsd[PC * PK * PC];            // dup'd deform weights [cin][k][cout]
__device__ double g_s1a[PB * 5], g_s2a[PB * 5];
__device__ double g_s1b[PB * 8], g_s2b[PB * 8];

// ---------------- reductions ----------------
__device__ __forceinline__ void block_reduce2_atomic(float v1, float v2,
                                                     double* d1, double* d2) {
    __shared__ float r1[8], r2[8];
    __syncthreads();
    #pragma unroll
    for (int o = 16; o; o >>= 1) {
        v1 += __shfl_down_sync(0xffffffffu, v1, o);
        v2 += __shfl_down_sync(0xffffffffu, v2, o);
    }
    int warp = threadIdx.x >> 5, lane = threadIdx.x & 31;
    if (lane == 0) { r1[warp] = v1; r2[warp] = v2; }
    __syncthreads();
    if (warp == 0) {
        v1 = (lane < 8) ? r1[lane] : 0.f;
        v2 = (lane < 8) ? r2[lane] : 0.f;
        #pragma unroll
        for (int o = 4; o; o >>= 1) {
            v1 += __shfl_down_sync(0xffffffffu, v1, o);
            v2 += __shfl_down_sync(0xffffffffu, v2, o);
        }
        if (lane == 0) { atomicAdd(d1, (double)v1); atomicAdd(d2, (double)v2); }
    }
}

// warp-level: destination must be uniform WITHIN a warp
__device__ __forceinline__ void warp_reduce2_atomic(float v1, float v2,
                                                    double* d1, double* d2) {
    #pragma unroll
    for (int o = 16; o; o >>= 1) {
        v1 += __shfl_down_sync(0xffffffffu, v1, o);
        v2 += __shfl_down_sync(0xffffffffu, v2, o);
    }
    if ((threadIdx.x & 31) == 0) {
        atomicAdd(d1, (double)v1);
        atomicAdd(d2, (double)v2);
    }
}

// ---------------- K0: zero accumulators + transpose/dup deform weights -----
__global__ void k_init(const float* __restrict__ w_dsc) {
    int gi = blockIdx.x * 256 + threadIdx.x;
    if (gi < PB * 5) { g_s1a[gi] = 0.0; g_s2a[gi] = 0.0; }
    if (gi < PB * 8) { g_s1b[gi] = 0.0; g_s2b[gi] = 0.0; }
    if (gi < PC * PK * PC) {
        int o = gi & 31; int r = gi >> 5;
        int k = r % 9; int cin = r / 9;
        g_wsd[gi] = pack2(w_dsc[(o * PC + cin) * 9 + k]);
    }
}

// ---------------- K1: 3x3 SAME conv (ch 0..9) + GN1 partial sums ----------
// block = 4 W-rows x full H. cp.async double-buffered per-cin staging.
__global__ __launch_bounds__(256) void k_conv1(const float* __restrict__ x,
                                               const float* __restrict__ w_off,
                                               const float* __restrict__ b_off) {
    __shared__ __align__(16) float wsf[PC * 9 * NCO];   // [cin][tap][10] 11520B
    __shared__ __align__(16) float xs[2][6][264];       // rows w0-1..w0+4, col c at idx 4+c

    int tid = threadIdx.x;
    int b  = blockIdx.y;
    int w0 = blockIdx.x * 4;
    int h  = tid;

    // weights: wsf[(cin*9+tap)*10 + c] = w_off[c][cin][tap]
    for (int i = tid; i < PC * 9 * NCO; i += 256) {
        int c = i % 10; int r = i / 10;
        int tap = r % 9; int cin = r / 9;
        wsf[i] = w_off[(c * PC + cin) * 9 + tap];
    }
    // zero halo columns (idx 0..3 and 260..263) in both buffers
    if (tid < 96) {
        int bu = tid / 48, rr = (tid / 8) % 6, e = tid & 7;
        int idx = (e < 4) ? e : 256 + e;
        xs[bu][rr][idx] = 0.f;
    }

    const float* xb = x + (size_t)b * PC * 65536;

    auto stage = [&](int cin) {
        int bu = cin & 1;
        #pragma unroll
        for (int j = 0; j < 2; j++) {
            int idx = tid + j * 256;
            if (idx < 384) {
                int rr = idx >> 6, c4 = idx & 63;
                int g = w0 - 1 + rr;
                if ((unsigned)g < 256u)
                    cp16(s2u(&xs[bu][rr][4 + c4 * 4]),
                         xb + (size_t)cin * 65536 + (g << 8) + c4 * 4);
                else
                    *(float4*)&xs[bu][rr][4 + c4 * 4] = make_float4(0.f, 0.f, 0.f, 0.f);
            }
        }
        asm volatile("cp.async.commit_group;");
    };

    ull acc[4][5];
    #pragma unroll
    for (int wl = 0; wl < 4; wl++)
        #pragma unroll
        for (int q = 0; q < 5; q++) acc[wl][q] = 0ull;

    stage(0);

    for (int cin = 0; cin < PC; cin++) {
        asm volatile("cp.async.wait_group 0;");
        __syncthreads();
        if (cin < 31) stage(cin + 1);
        int bu = cin & 1;

        float xv[6][3];
        #pragma unroll
        for (int rr = 0; rr < 6; rr++)
            #pragma unroll
            for (int dj = 0; dj < 3; dj++)
                xv[rr][dj] = xs[bu][rr][3 + h + dj];

        #pragma unroll
        for (int di = 0; di < 3; di++) {
            #pragma unroll
            for (int dj = 0; dj < 3; dj++) {
                const ull* wp = (const ull*)&wsf[(cin * 9 + di * 3 + dj) * 10];
                ull q0 = wp[0], q1 = wp[1], q2 = wp[2], q3 = wp[3], q4 = wp[4];
                #pragma unroll
                for (int wl = 0; wl < 4; wl++) {
                    ull xx2 = pack2(xv[wl + di][dj]);
                    fma2(acc[wl][0], q0, xx2);
                    fma2(acc[wl][1], q1, xx2);
                    fma2(acc[wl][2], q2, xx2);
                    fma2(acc[wl][3], q3, xx2);
                    fma2(acc[wl][4], q4, xx2);
                }
            }
        }
    }

    float p1[5], p2[5];
    #pragma unroll
    for (int q = 0; q < 5; q++) { p1[q] = 0.f; p2[q] = 0.f; }
    #pragma unroll
    for (int wl = 0; wl < 4; wl++) {
        int gi = w0 + wl;
        #pragma unroll
        for (int q = 0; q < 5; q++) {
            float2 f = unpack2(acc[wl][q]);
            float v0 = f.x + b_off[2 * q];
            float v1 = f.y + b_off[2 * q + 1];
            g_off[(size_t)((b * NCO + 2 * q)     << 16) + (gi << 8) + h] = v0;
            g_off[(size_t)((b * NCO + 2 * q + 1) << 16) + (gi << 8) + h] = v1;
            p1[q] += v0 + v1;
            p2[q] += v0 * v0 + v1 * v1;
        }
    }
    for (int q = 0; q < 5; q++)
        block_reduce2_atomic(p1[q], p2[q], &g_s1a[b * 5 + q], &g_s2a[b * 5 + q]);
}

// ---------------- K3: py (inline) + deformable gather + GEMM + GN2 sums ----
// Block=(w,b). SMEM bytes:
//   ds   [4][9][256] f32        @ 0      (36864)
//   rows [4][11][256] f32       @ 36864  (45056)
//   wsd  [2][4*9*32] ull (dup)  @ 81920  (18432)
//   A1s/B1s [10]+[10] f32       @ 100352 (80)
#define DS_OFF   0
#define ROWS_OFF 36864
#define WSD_OFF  81920
#define A1_OFF   100352
#define K3_SMEM  100448

__global__ __launch_bounds__(256, 2) void k_deform(const float* __restrict__ x,
                                                   const float* __restrict__ b_dsc,
                                                   const float* __restrict__ gos,
                                                   const float* __restrict__ gob,
                                                   float* __restrict__ out) {
    extern __shared__ __align__(16) char smem[];
    float* ds   = (float*)(smem + DS_OFF);
    float* rows = (float*)(smem + ROWS_OFF);
    ull*   wsd  = (ull*)  (smem + WSD_OFF);
    float* A1s  = (float*)(smem + A1_OFF);
    float* B1s  = A1s + 10;
    unsigned su = s2u(smem);

    int tid = threadIdx.x;
    int w = blockIdx.x;
    int b = blockIdx.y;
    const float* xb = x + ((size_t)(b * PC) << 16);

    // ---- staging (cp.async) ----
    auto stage = [&](int c) {
        int cin0 = c * 4;
        #pragma unroll
        for (int j = 0; j < 11; j++) {
            int i4 = tid + j * 256;             // < 2816
            int rid = i4 >> 6;                  // cl*11+rr
            int c4 = i4 & 63;
            int cl = rid / 11;
            int rr = rid - cl * 11;
            int g = min(max(w - 5 + rr, 0), 255);
            cp16(su + ROWS_OFF + ((rid << 8) + (c4 << 2)) * 4,
                 xb + (((size_t)(cin0 + cl)) << 16) + (g << 8) + (c4 << 2));
        }
        #pragma unroll
        for (int j = 0; j < 3; j++) {
            int i = tid + j * 256;
            if (i < 576)
                cp16(su + WSD_OFF + ((c & 1) * 1152 + i * 2) * 8,
                     g_wsd + cin0 * 9 * 32 + i * 2);
        }
        asm volatile("cp.async.commit_group;");
    };

    stage(0);   // overlap with py computation below

    // ---- GN1 affine from global sums ----
    if (tid < 10) {
        int g = tid >> 1;
        double N = 131072.0;
        double mu = g_s1a[b * 5 + g] / N;
        double var = g_s2a[b * 5 + g] / N - mu * mu;
        float rstd = rsqrtf((float)var + EPS);
        float A = gos[tid] * rstd;
        A1s[tid] = A;
        B1s[tid] = gob[tid] - (float)mu * A;
    }
    __syncthreads();

    // ---- py for h = tid, all 9 k (kept in registers; same thread gathers) --
    float wyr[PK];
    int   r0r[PK];
    {
        float t[PK];
        #pragma unroll
        for (int c = 0; c < PK; c++) {
            float v = g_off[(size_t)((b * NCO + c) << 16) + (w << 8) + tid];
            t[c] = tanhf(fmaf(v, A1s[c], B1s[c]));
        }
        float cum[PK];
        cum[3] = t[3];
        cum[2] = t[2] + cum[3];
        cum[1] = t[1] + cum[2];
        cum[0] = t[0] + cum[1];
        cum[4] = 0.f;
        cum[5] = t[5];
        cum[6] = cum[5] + t[6];
        cum[7] = cum[6] + t[7];
        cum[8] = cum[7] + t[8];
        #pragma unroll
        for (int k = 0; k < PK; k++) {
            float yn = (float)w + cum[k];
            float py = fminf(fmaxf(yn, 0.f), 256.f) * (255.0f / 256.0f);
            float y0f = floorf(py);
            wyr[k] = py - y0f;
            r0r[k] = (int)y0f - w + 5;          // in [0,9]
        }
    }

    int co0 = (tid >> 6) * 8;       // uniform per 64-thread group
    int h0  = (tid & 63) * 4;
    ull acc[8][2];
    #pragma unroll
    for (int i = 0; i < 8; i++) { acc[i][0] = 0ull; acc[i][1] = 0ull; }

    for (int c = 0; c < 8; c++) {
        asm volatile("cp.async.wait_group 0;");
        __syncthreads();                         // rows/ws ready; ds free

        // ---- gather from staged rows (analytic px, conflict-free LDS) ----
        #pragma unroll
        for (int k = 0; k < PK; k++) {
            float wy = wyr[k];
            int r0 = r0r[k];
            int r1 = r0 + 1;                     // staging clamp makes this exact
            int t = min(max(tid + k - CENTER, 0), 256);
            int x0 = max(t - 1, 0);
            int x1 = min(t, 255);
            float wx = (t > 0) ? (1.0f - (float)t * 0.00390625f) : 0.0f;
            #pragma unroll
            for (int cl = 0; cl < 4; cl++) {
                const float* rp0 = rows + ((cl * RROWS + r0) << 8);
                const float* rp1 = rows + ((cl * RROWS + r1) << 8);
                float v00 = rp0[x0], v01 = rp0[x1];
                float v10 = rp1[x0], v11 = rp1[x1];
                float vx0 = v00 + wx * (v01 - v00);
                float vx1 = v10 + wx * (v11 - v10);
                ds[((cl * 9 + k) << 8) + tid] = vx0 + wy * (vx1 - vx0);
            }
        }
        __syncthreads();                         // ds ready; rows consumed
        if (c < 7) stage(c + 1);

        // ---- GEMM: h-paired FFMA2, broadcast dup'd weights ----
        const ull* wb = wsd + (c & 1) * 1152;
        #pragma unroll
        for (int cl = 0; cl < 4; cl++) {
            #pragma unroll
            for (int k = 0; k < 9; k++) {
                const ull* wp = wb + ((cl * 9 + k) << 5) + co0;
                ulonglong2 wa = *(const ulonglong2*)(wp);
                ulonglong2 wbb = *(const ulonglong2*)(wp + 2);
                ulonglong2 wc = *(const ulonglong2*)(wp + 4);
                ulonglong2 wd = *(const ulonglong2*)(wp + 6);
                ulonglong2 dv = *(const ulonglong2*)(ds + ((cl * 9 + k) << 8) + h0);
                fma2(acc[0][0], wa.x, dv.x);  fma2(acc[0][1], wa.x, dv.y);
                fma2(acc[1][0], wa.y, dv.x);  fma2(acc[1][1], wa.y, dv.y);
                fma2(acc[2][0], wbb.x, dv.x); fma2(acc[2][1], wbb.x, dv.y);
                fma2(acc[3][0], wbb.y, dv.x); fma2(acc[3][1], wbb.y, dv.y);
                fma2(acc[4][0], wc.x, dv.x);  fma2(acc[4][1], wc.x, dv.y);
                fma2(acc[5][0], wc.y, dv.x);  fma2(acc[5][1], wc.y, dv.y);
                fma2(acc[6][0], wd.x, dv.x);  fma2(acc[6][1], wd.x, dv.y);
                fma2(acc[7][0], wd.y, dv.x);  fma2(acc[7][1], wd.y, dv.y);
            }
        }
    }

    // ---- epilogue: bias, store, fused GN2 partial sums (warp-level) ----
    float sa1 = 0.f, sa2 = 0.f, sb1 = 0.f, sb2 = 0.f;
    #pragma unroll
    for (int i = 0; i < 8; i++) {
        int o = co0 + i;
        float bo = b_dsc[o];
        float2 f01 = unpack2(acc[i][0]);
        float2 f23 = unpack2(acc[i][1]);
        float v0 = f01.x + bo, v1 = f01.y + bo;
        float v2 = f23.x + bo, v3 = f23.y + bo;
        float4 r = make_float4(v0, v1, v2, v3);
        *(float4*)&out[((size_t)(b * PC + o) << 16) + (w << 8) + h0] = r;
        float s = v0 + v1 + v2 + v3;
        float q = v0 * v0 + v1 * v1 + v2 * v2 + v3 * v3;
        if (i < 4) { sa1 += s; sa2 += q; } else { sb1 += s; sb2 += q; }
    }
    int g0 = co0 >> 2;   // warp-uniform
    warp_reduce2_atomic(sa1, sa2, &g_s1b[b * 8 + g0],     &g_s2b[b * 8 + g0]);
    warp_reduce2_atomic(sb1, sb2, &g_s1b[b * 8 + g0 + 1], &g_s2b[b * 8 + g0 + 1]);
}

// ---------------- K5: GN2 affine (inline) + relu in place ----------------
__global__ __launch_bounds__(256) void k_relu(float* __restrict__ out,
                                              const float* __restrict__ gs,
                                              const float* __restrict__ gb) {
    int i4 = blockIdx.x * 256 + threadIdx.x;
    int bc = i4 >> 14;
    int b = bc >> 5, c = bc & 31, g = c >> 2;
    double N = 262144.0;
    double mu = g_s1b[b * 8 + g] / N;
    double var = g_s2b[b * 8 + g] / N - mu * mu;
    float rstd = rsqrtf((float)var + EPS);
    float A = gs[c] * rstd;
    float Bv = gb[c] - (float)mu * A;
    float4 v = ((float4*)out)[i4];
    v.x = fmaxf(v.x * A + Bv, 0.f);
    v.y = fmaxf(v.y * A + Bv, 0.f);
    v.z = fmaxf(v.z * A + Bv, 0.f);
    v.w = fmaxf(v.w * A + Bv, 0.f);
    ((float4*)out)[i4] = v;
}

// ---------------- launch ----------------
extern "C" void kernel_launch(void* const* d_in, const int* in_sizes, int n_in,
                              void* d_out, int out_size) {
    const float* x      = (const float*)d_in[0];
    const float* w_off  = (const float*)d_in[1];
    const float* b_off  = (const float*)d_in[2];
    const float* gos    = (const float*)d_in[3];
    const float* gob    = (const float*)d_in[4];
    const float* w_dsc  = (const float*)d_in[5];
    const float* b_dsc  = (const float*)d_in[6];
    const float* gs     = (const float*)d_in[7];
    const float* gb     = (const float*)d_in[8];
    float* out = (float*)d_out;

    cudaFuncSetAttribute(k_deform, cudaFuncAttributeMaxDynamicSharedMemorySize, K3_SMEM);

    k_init<<<36, 256>>>(w_dsc);
    k_conv1<<<dim3(64, PB), 256>>>(x, w_off, b_off);
    k_deform<<<dim3(256, PB), 256, K3_SMEM>>>(x, b_dsc, gos, gob, out);
    k_relu<<<8192, 256>>>(out, gs, gb);
}

// round 8
// speedup vs baseline: 3.5064x; 1.1010x over previous
#include <cuda_runtime.h>
#include <cuda_bf16.h>
#include <math.h>

// Problem constants
#define PB 4
#define PC 32
#define PW 256
#define PH 256
#define PK 9
#define CENTER 4
#define EPS 1e-5f

#define NCO 10   // conv1 output channels needed (0..9)
#define RROWS 11 // rows staged per (b,w) deform block: y in [w-5, w+5]

typedef unsigned long long ull;
typedef unsigned char uchar;

// ---------------- f32x2 helpers (FFMA2 — 2x fp32 rate on sm_103a) ----------
__device__ __forceinline__ ull pack2(float v) {
    ull r; asm("mov.b64 %0,{%1,%1};" : "=l"(r) : "f"(v)); return r;
}
__device__ __forceinline__ void fma2(ull& acc, ull a, ull b) {
    asm("fma.rn.f32x2 %0,%1,%2,%0;" : "+l"(acc) : "l"(a), "l"(b));
}
__device__ __forceinline__ float2 unpack2(ull v) {
    float2 f; asm("mov.b64 {%0,%1},%2;" : "=f"(f.x), "=f"(f.y) : "l"(v)); return f;
}
__device__ __forceinline__ void cp16(unsigned sdst, const void* gsrc) {
    asm volatile("cp.async.cg.shared.global [%0], [%1], 16;" :: "r"(sdst), "l"(gsrc));
}
__device__ __forceinline__ unsigned s2u(const void* p) {
    unsigned a;
    asm("{ .reg .u64 t; cvta.to.shared.u64 t, %1; cvt.u32.u64 %0, t; }" : "=r"(a) : "l"(p));
    return a;
}

// ---------------- scratch ----------------
__device__ float g_off[PB * NCO * PW * PH];
__device__ ull   g_wsd[PC * PK * PC];            // dup'd deform weights [cin][k][cout]
__device__ double g_s1a[PB * 5], g_s2a[PB * 5];
__device__ double g_s1b[PB * 8], g_s2b[PB * 8];

// ---------------- reductions ----------------
__device__ __forceinline__ void block_reduce2_atomic(float v1, float v2,
                                                     double* d1, double* d2) {
    __shared__ float r1[8], r2[8];
    __syncthreads();
    #pragma unroll
    for (int o = 16; o; o >>= 1) {
        v1 += __shfl_down_sync(0xffffffffu, v1, o);
        v2 += __shfl_down_sync(0xffffffffu, v2, o);
    }
    int warp = threadIdx.x >> 5, lane = threadIdx.x & 31;
    if (lane == 0) { r1[warp] = v1; r2[warp] = v2; }
    __syncthreads();
    if (warp == 0) {
        v1 = (lane < 8) ? r1[lane] : 0.f;
        v2 = (lane < 8) ? r2[lane] : 0.f;
        #pragma unroll
        for (int o = 4; o; o >>= 1) {
            v1 += __shfl_down_sync(0xffffffffu, v1, o);
            v2 += __shfl_down_sync(0xffffffffu, v2, o);
        }
        if (lane == 0) { atomicAdd(d1, (double)v1); atomicAdd(d2, (double)v2); }
    }
}

// warp-level: destination must be uniform WITHIN a warp
__device__ __forceinline__ void warp_reduce2_atomic(float v1, float v2,
                                                    double* d1, double* d2) {
    #pragma unroll
    for (int o = 16; o; o >>= 1) {
        v1 += __shfl_down_sync(0xffffffffu, v1, o);
        v2 += __shfl_down_sync(0xffffffffu, v2, o);
    }
    if ((threadIdx.x & 31) == 0) {
        atomicAdd(d1, (double)v1);
        atomicAdd(d2, (double)v2);
    }
}

// ---------------- K0: zero accumulators + transpose/dup deform weights -----
__global__ void k_init(const float* __restrict__ w_dsc) {
    int gi = blockIdx.x * 256 + threadIdx.x;
    if (gi < PB * 5) { g_s1a[gi] = 0.0; g_s2a[gi] = 0.0; }
    if (gi < PB * 8) { g_s1b[gi] = 0.0; g_s2b[gi] = 0.0; }
    if (gi < PC * PK * PC) {
        int o = gi & 31; int r = gi >> 5;
        int k = r % 9; int cin = r / 9;
        g_wsd[gi] = pack2(w_dsc[(o * PC + cin) * 9 + k]);
    }
}

// ---------------- K1: 3x3 SAME conv (ch 0..9) + GN1 partial sums ----------
// block = 4 W-rows x full H, 2 blocks/SM -> single wave + cross-block overlap.
__global__ __launch_bounds__(256, 2) void k_conv1(const float* __restrict__ x,
                                                  const float* __restrict__ w_off,
                                                  const float* __restrict__ b_off) {
    __shared__ __align__(16) float wsf[PC * 9 * NCO];   // [cin][tap][10] 11520B
    __shared__ __align__(16) float xs[2][6][264];       // rows w0-1..w0+4, col c at idx 4+c

    int tid = threadIdx.x;
    int b  = blockIdx.y;
    int w0 = blockIdx.x * 4;
    int h  = tid;

    for (int i = tid; i < PC * 9 * NCO; i += 256) {
        int c = i % 10; int r = i / 10;
        int tap = r % 9; int cin = r / 9;
        wsf[i] = w_off[(c * PC + cin) * 9 + tap];
    }
    if (tid < 96) {
        int bu = tid / 48, rr = (tid / 8) % 6, e = tid & 7;
        int idx = (e < 4) ? e : 256 + e;
        xs[bu][rr][idx] = 0.f;
    }

    const float* xb = x + (size_t)b * PC * 65536;

    auto stage = [&](int cin) {
        int bu = cin & 1;
        #pragma unroll
        for (int j = 0; j < 2; j++) {
            int idx = tid + j * 256;
            if (idx < 384) {
                int rr = idx >> 6, c4 = idx & 63;
                int g = w0 - 1 + rr;
                if ((unsigned)g < 256u)
                    cp16(s2u(&xs[bu][rr][4 + c4 * 4]),
                         xb + (size_t)cin * 65536 + (g << 8) + c4 * 4);
                else
                    *(float4*)&xs[bu][rr][4 + c4 * 4] = make_float4(0.f, 0.f, 0.f, 0.f);
            }
        }
        asm volatile("cp.async.commit_group;");
    };

    ull acc[4][5];
    #pragma unroll
    for (int wl = 0; wl < 4; wl++)
        #pragma unroll
        for (int q = 0; q < 5; q++) acc[wl][q] = 0ull;

    stage(0);

    for (int cin = 0; cin < PC; cin++) {
        asm volatile("cp.async.wait_group 0;");
        __syncthreads();
        if (cin < 31) stage(cin + 1);
        int bu = cin & 1;

        float xv[6][3];
        #pragma unroll
        for (int rr = 0; rr < 6; rr++)
            #pragma unroll
            for (int dj = 0; dj < 3; dj++)
                xv[rr][dj] = xs[bu][rr][3 + h + dj];

        #pragma unroll
        for (int di = 0; di < 3; di++) {
            #pragma unroll
            for (int dj = 0; dj < 3; dj++) {
                const ull* wp = (const ull*)&wsf[(cin * 9 + di * 3 + dj) * 10];
                ull q0 = wp[0], q1 = wp[1], q2 = wp[2], q3 = wp[3], q4 = wp[4];
                #pragma unroll
                for (int wl = 0; wl < 4; wl++) {
                    ull xx2 = pack2(xv[wl + di][dj]);
                    fma2(acc[wl][0], q0, xx2);
                    fma2(acc[wl][1], q1, xx2);
                    fma2(acc[wl][2], q2, xx2);
                    fma2(acc[wl][3], q3, xx2);
                    fma2(acc[wl][4], q4, xx2);
                }
            }
        }
    }

    float p1[5], p2[5];
    #pragma unroll
    for (int q = 0; q < 5; q++) { p1[q] = 0.f; p2[q] = 0.f; }
    #pragma unroll
    for (int wl = 0; wl < 4; wl++) {
        int gi = w0 + wl;
        #pragma unroll
        for (int q = 0; q < 5; q++) {
            float2 f = unpack2(acc[wl][q]);
            float v0 = f.x + b_off[2 * q];
            float v1 = f.y + b_off[2 * q + 1];
            g_off[(size_t)((b * NCO + 2 * q)     << 16) + (gi << 8) + h] = v0;
            g_off[(size_t)((b * NCO + 2 * q + 1) << 16) + (gi << 8) + h] = v1;
            p1[q] += v0 + v1;
            p2[q] += v0 * v0 + v1 * v1;
        }
    }
    for (int q = 0; q < 5; q++)
        block_reduce2_atomic(p1[q], p2[q], &g_s1a[b * 5 + q], &g_s2a[b * 5 + q]);
}

// ---------------- K3: py (inline) + deformable gather + GEMM + GN2 sums ----
#define DS_OFF   0
#define ROWS_OFF 36864
#define WSD_OFF  81920
#define A1_OFF   100352
#define K3_SMEM  100448

__global__ __launch_bounds__(256, 2) void k_deform(const float* __restrict__ x,
                                                   const float* __restrict__ b_dsc,
                                                   const float* __restrict__ gos,
                                                   const float* __restrict__ gob,
                                                   float* __restrict__ out) {
    extern __shared__ __align__(16) char smem[];
    float* ds   = (float*)(smem + DS_OFF);
    float* rows = (float*)(smem + ROWS_OFF);
    ull*   wsd  = (ull*)  (smem + WSD_OFF);
    float* A1s  = (float*)(smem + A1_OFF);
    float* B1s  = A1s + 10;
    unsigned su = s2u(smem);

    int tid = threadIdx.x;
    int w = blockIdx.x;
    int b = blockIdx.y;
    const float* xb = x + ((size_t)(b * PC) << 16);

    auto stage = [&](int c) {
        int cin0 = c * 4;
        #pragma unroll
        for (int j = 0; j < 11; j++) {
            int i4 = tid + j * 256;
            int rid = i4 >> 6;
            int c4 = i4 & 63;
            int cl = rid / 11;
            int rr = rid - cl * 11;
            int g = min(max(w - 5 + rr, 0), 255);
            cp16(su + ROWS_OFF + ((rid << 8) + (c4 << 2)) * 4,
                 xb + (((size_t)(cin0 + cl)) << 16) + (g << 8) + (c4 << 2));
        }
        #pragma unroll
        for (int j = 0; j < 3; j++) {
            int i = tid + j * 256;
            if (i < 576)
                cp16(su + WSD_OFF + ((c & 1) * 1152 + i * 2) * 8,
                     g_wsd + cin0 * 9 * 32 + i * 2);
        }
        asm volatile("cp.async.commit_group;");
    };

    stage(0);

    // ---- GN1 affine from global sums (fp32 math on converted sums) ----
    if (tid < 10) {
        int g = tid >> 1;
        float s1 = __double2float_rn(g_s1a[b * 5 + g]);
        float s2 = __double2float_rn(g_s2a[b * 5 + g]);
        float mu = s1 * (1.0f / 131072.0f);
        float var = s2 * (1.0f / 131072.0f) - mu * mu;
        float rstd = rsqrtf(var + EPS);
        float A = gos[tid] * rstd;
        A1s[tid] = A;
        B1s[tid] = gob[tid] - mu * A;
    }
    __syncthreads();

    // ---- py for h = tid (registers; same thread gathers) + hoisted px ----
    float wyr[PK];
    int   r0r[PK];
    float wxk[PK];
    int   x0k[PK], x1k[PK];
    {
        float t[PK];
        #pragma unroll
        for (int c = 0; c < PK; c++) {
            float v = g_off[(size_t)((b * NCO + c) << 16) + (w << 8) + tid];
            t[c] = tanhf(fmaf(v, A1s[c], B1s[c]));
        }
        float cum[PK];
        cum[3] = t[3];
        cum[2] = t[2] + cum[3];
        cum[1] = t[1] + cum[2];
        cum[0] = t[0] + cum[1];
        cum[4] = 0.f;
        cum[5] = t[5];
        cum[6] = cum[5] + t[6];
        cum[7] = cum[6] + t[7];
        cum[8] = cum[7] + t[8];
        #pragma unroll
        for (int k = 0; k < PK; k++) {
            float yn = (float)w + cum[k];
            float py = fminf(fmaxf(yn, 0.f), 256.f) * (255.0f / 256.0f);
            float y0f = floorf(py);
            wyr[k] = py - y0f;
            r0r[k] = (int)y0f - w + 5;          // in [0,9]
            int tt = min(max(tid + k - CENTER, 0), 256);
            x0k[k] = max(tt - 1, 0);
            x1k[k] = min(tt, 255);
            wxk[k] = (tt > 0) ? (1.0f - (float)tt * 0.00390625f) : 0.0f;
        }
    }

    int co0 = (tid >> 6) * 8;
    int h0  = (tid & 63) * 4;
    ull acc[8][2];
    #pragma unroll
    for (int i = 0; i < 8; i++) { acc[i][0] = 0ull; acc[i][1] = 0ull; }

    for (int c = 0; c < 8; c++) {
        asm volatile("cp.async.wait_group 0;");
        __syncthreads();

        // ---- gather from staged rows (hoisted px params) ----
        #pragma unroll
        for (int k = 0; k < PK; k++) {
            float wy = wyr[k];
            int r0 = r0r[k];
            int r1 = r0 + 1;
            int x0 = x0k[k], x1 = x1k[k];
            float wx = wxk[k];
            #pragma unroll
            for (int cl = 0; cl < 4; cl++) {
                const float* rp0 = rows + ((cl * RROWS + r0) << 8);
                const float* rp1 = rows + ((cl * RROWS + r1) << 8);
                float v00 = rp0[x0], v01 = rp0[x1];
                float v10 = rp1[x0], v11 = rp1[x1];
                float vx0 = v00 + wx * (v01 - v00);
                float vx1 = v10 + wx * (v11 - v10);
                ds[((cl * 9 + k) << 8) + tid] = vx0 + wy * (vx1 - vx0);
            }
        }
        __syncthreads();
        if (c < 7) stage(c + 1);

        // ---- GEMM: h-paired FFMA2, broadcast dup'd weights ----
        const ull* wb = wsd + (c & 1) * 1152;
        #pragma unroll
        for (int cl = 0; cl < 4; cl++) {
            #pragma unroll
            for (int k = 0; k < 9; k++) {
                const ull* wp = wb + ((cl * 9 + k) << 5) + co0;
                ulonglong2 wa = *(const ulonglong2*)(wp);
                ulonglong2 wbb = *(const ulonglong2*)(wp + 2);
                ulonglong2 wc = *(const ulonglong2*)(wp + 4);
                ulonglong2 wd = *(const ulonglong2*)(wp + 6);
                ulonglong2 dv = *(const ulonglong2*)(ds + ((cl * 9 + k) << 8) + h0);
                fma2(acc[0][0], wa.x, dv.x);  fma2(acc[0][1], wa.x, dv.y);
                fma2(acc[1][0], wa.y, dv.x);  fma2(acc[1][1], wa.y, dv.y);
                fma2(acc[2][0], wbb.x, dv.x); fma2(acc[2][1], wbb.x, dv.y);
                fma2(acc[3][0], wbb.y, dv.x); fma2(acc[3][1], wbb.y, dv.y);
                fma2(acc[4][0], wc.x, dv.x);  fma2(acc[4][1], wc.x, dv.y);
                fma2(acc[5][0], wc.y, dv.x);  fma2(acc[5][1], wc.y, dv.y);
                fma2(acc[6][0], wd.x, dv.x);  fma2(acc[6][1], wd.x, dv.y);
                fma2(acc[7][0], wd.y, dv.x);  fma2(acc[7][1], wd.y, dv.y);
            }
        }
    }

    // ---- epilogue: bias, store, fused GN2 partial sums (warp-level) ----
    float sa1 = 0.f, sa2 = 0.f, sb1 = 0.f, sb2 = 0.f;
    #pragma unroll
    for (int i = 0; i < 8; i++) {
        int o = co0 + i;
        float bo = b_dsc[o];
        float2 f01 = unpack2(acc[i][0]);
        float2 f23 = unpack2(acc[i][1]);
        float v0 = f01.x + bo, v1 = f01.y + bo;
        float v2 = f23.x + bo, v3 = f23.y + bo;
        float4 r = make_float4(v0, v1, v2, v3);
        *(float4*)&out[((size_t)(b * PC + o) << 16) + (w << 8) + h0] = r;
        float s = v0 + v1 + v2 + v3;
        float q = v0 * v0 + v1 * v1 + v2 * v2 + v3 * v3;
        if (i < 4) { sa1 += s; sa2 += q; } else { sb1 += s; sb2 += q; }
    }
    int g0 = co0 >> 2;
    warp_reduce2_atomic(sa1, sa2, &g_s1b[b * 8 + g0],     &g_s2b[b * 8 + g0]);
    warp_reduce2_atomic(sb1, sb2, &g_s1b[b * 8 + g0 + 1], &g_s2b[b * 8 + g0 + 1]);
}

// ---------------- K5: GN2 affine (fp32) + relu in place ----------------
__global__ __launch_bounds__(256) void k_relu(float* __restrict__ out,
                                              const float* __restrict__ gs,
                                              const float* __restrict__ gb) {
    int i4 = blockIdx.x * 256 + threadIdx.x;
    int bc = i4 >> 14;
    int b = bc >> 5, c = bc & 31, g = c >> 2;
    float s1 = __double2float_rn(g_s1b[b * 8 + g]);
    float s2 = __double2float_rn(g_s2b[b * 8 + g]);
    float mu = s1 * (1.0f / 262144.0f);
    float var = s2 * (1.0f / 262144.0f) - mu * mu;
    float rstd = rsqrtf(var + EPS);
    float A = gs[c] * rstd;
    float Bv = gb[c] - mu * A;
    float4 v = ((float4*)out)[i4];
    v.x = fmaxf(v.x * A + Bv, 0.f);
    v.y = fmaxf(v.y * A + Bv, 0.f);
    v.z = fmaxf(v.z * A + Bv, 0.f);
    v.w = fmaxf(v.w * A + Bv, 0.f);
    ((float4*)out)[i4] = v;
}

// ---------------- launch ----------------
extern "C" void kernel_launch(void* const* d_in, const int* in_sizes, int n_in,
                              void* d_out, int out_size) {
    const float* x      = (const float*)d_in[0];
    const float* w_off  = (const float*)d_in[1];
    const float* b_off  = (const float*)d_in[2];
    const float* gos    = (const float*)d_in[3];
    const float* gob    = (const float*)d_in[4];
    const float* w_dsc  = (const float*)d_in[5];
    const float* b_dsc  = (const float*)d_in[6];
    const float* gs     = (const float*)d_in[7];
    const float* gb     = (const float*)d_in[8];
    float* out = (float*)d_out;

    cudaFuncSetAttribute(k_deform, cudaFuncAttributeMaxDynamicSharedMemorySize, K3_SMEM);

    k_init<<<36, 256>>>(w_dsc);
    k_conv1<<<dim3(64, PB), 256>>>(x, w_off, b_off);
    k_deform<<<dim3(256, PB), 256, K3_SMEM>>>(x, b_dsc, gos, gob, out);
    k_relu<<<8192, 256>>>(out, gs, gb);
}